// round 1
// baseline (speedup 1.0000x reference)
#include <cuda_runtime.h>

// BroadcastTC: per (b,c) pair (B*C = 1,048,576 pairs), with t1,t2 of 27 fp32:
//   out1[x,y,u,v] = sum_k t1[x,y,k]*t2[k,u,v] / sqrt(3)     (81 floats/pair)
//   out2[x,u]     = sum_{k,l} t1[x,k,l]*t2[k,l,u] / 3       (9 floats/pair)
//   out3          = sum_i t1[i]*t2[i] / sqrt(27)            (1 float/pair)
// Output buffer layout: [out1 flat | out2 flat | out3 flat].

#define PAIRS_PER_BLOCK 128
#define THREADS 128

__global__ __launch_bounds__(THREADS)
void broadcast_tc_kernel(const float* __restrict__ T1,
                         const float* __restrict__ T2,
                         float* __restrict__ out,
                         int npairs)
{
    __shared__ float s1[PAIRS_PER_BLOCK * 27];
    __shared__ float s2[PAIRS_PER_BLOCK * 27];

    const int tid = threadIdx.x;
    const long long block_pair0 = (long long)blockIdx.x * PAIRS_PER_BLOCK;

    // Coalesced staging: 128*27 = 3456 contiguous floats per array per block.
    const float* g1 = T1 + block_pair0 * 27;
    const float* g2 = T2 + block_pair0 * 27;
    const int nelem = PAIRS_PER_BLOCK * 27;
    #pragma unroll
    for (int i = tid; i < nelem; i += THREADS) {
        s1[i] = g1[i];
        s2[i] = g2[i];
    }
    __syncthreads();

    const long long pair = block_pair0 + tid;
    if (pair >= npairs) return;

    // Stride-27 smem reads: 27 coprime to 32 -> conflict-free.
    float a[27], b[27];
    #pragma unroll
    for (int j = 0; j < 27; j++) {
        a[j] = s1[tid * 27 + j];
        b[j] = s2[tid * 27 + j];
    }

    const float n1 = 0.5773502691896258f;   // 1/sqrt(3)
    const float n2 = 0.3333333333333333f;   // 1/3
    const float n3 = 0.1924500897298753f;   // 1/sqrt(27)

    float* __restrict__ o1 = out + pair * 81;
    float* __restrict__ o2 = out + (long long)npairs * 81 + pair * 9;
    float* __restrict__ o3 = out + (long long)npairs * 90 + pair;

    // out1: for each (x,y) pick 3 coeffs of t1, combine with t2 rows.
    #pragma unroll
    for (int xy = 0; xy < 9; xy++) {
        const float c0 = a[xy * 3 + 0];
        const float c1 = a[xy * 3 + 1];
        const float c2 = a[xy * 3 + 2];
        #pragma unroll
        for (int uv = 0; uv < 9; uv++) {
            float r = c0 * b[uv] + c1 * b[9 + uv] + c2 * b[18 + uv];
            o1[xy * 9 + uv] = r * n1;
        }
    }

    // out2[x,u] = sum_{kl=0..8} t1[x*9+kl] * t2[3*kl+u]
    #pragma unroll
    for (int x = 0; x < 3; x++) {
        #pragma unroll
        for (int u = 0; u < 3; u++) {
            float r = 0.0f;
            #pragma unroll
            for (int kl = 0; kl < 9; kl++) {
                r += a[x * 9 + kl] * b[3 * kl + u];
            }
            o2[x * 3 + u] = r * n2;
        }
    }

    // out3: full dot product.
    float r3 = 0.0f;
    #pragma unroll
    for (int j = 0; j < 27; j++) r3 += a[j] * b[j];
    *o3 = r3 * n3;
}

extern "C" void kernel_launch(void* const* d_in, const int* in_sizes, int n_in,
                              void* d_out, int out_size)
{
    const float* T1 = (const float*)d_in[0];
    const float* T2 = (const float*)d_in[1];
    float* out = (float*)d_out;

    const int npairs = in_sizes[0] / 27;           // B*C
    const int grid = (npairs + PAIRS_PER_BLOCK - 1) / PAIRS_PER_BLOCK;

    broadcast_tc_kernel<<<grid, THREADS>>>(T1, T2, out, npairs);
}

// round 2
// speedup vs baseline: 4.1391x; 4.1391x over previous
#include <cuda_runtime.h>

// BroadcastTC on GB300. Per (b,c) pair (npairs = B*C = 1,048,576), with
// t1,t2 of 27 fp32 each:
//   out1[xy,uv] = sum_k t1[xy*3+k] * t2[k*9+uv] / sqrt(3)   (81 floats)
//   out2[x,u]   = sum_kl t1[x*9+kl] * t2[kl*3+u] / 3        (9 floats)
//   out3        = dot(t1,t2) / sqrt(27)                     (1 float)
// Output layout: [out1 flat | out2 flat | out3 flat].
//
// Strategy (L1-wavefront bound fix, round 2): stage inputs in smem,
// assign threads to OUTPUT addresses (not pairs) so all global stores are
// fully coalesced float4 STG.128. A block owns 64 consecutive pairs, whose
// out1 region is 5184 contiguous floats.

#define PPB 64        // pairs per block (npairs divisible: 2^20 / 64)
#define THREADS 256

__global__ __launch_bounds__(THREADS)
void broadcast_tc_kernel(const float* __restrict__ T1,
                         const float* __restrict__ T2,
                         float* __restrict__ out,
                         int npairs)
{
    __shared__ float s1[PPB * 27];   // 6912 B
    __shared__ float s2[PPB * 27];   // 6912 B

    const int tid = threadIdx.x;
    const long long p0 = (long long)blockIdx.x * PPB;

    // ---- Stage inputs: 64*27 = 1728 floats = 432 float4 per array ----
    {
        const float4* g1 = (const float4*)(T1 + p0 * 27);
        const float4* g2 = (const float4*)(T2 + p0 * 27);
        float4* s1v = (float4*)s1;
        float4* s2v = (float4*)s2;
        #pragma unroll
        for (int i = tid; i < PPB * 27 / 4; i += THREADS) {
            s1v[i] = g1[i];
            s2v[i] = g2[i];
        }
    }
    __syncthreads();

    const float n1 = 0.5773502691896258f;   // 1/sqrt(3)
    const float n2 = 0.3333333333333333f;   // 1/3
    const float n3 = 0.1924500897298753f;   // 1/sqrt(27)

    // ---- out1: 64*81 = 5184 floats = 1296 float4, fully coalesced ----
    {
        float4* o1 = (float4*)(out + p0 * 81);
        #pragma unroll
        for (int v = tid; v < PPB * 81 / 4; v += THREADS) {
            float4 r;
            float* rr = (float*)&r;
            #pragma unroll
            for (int e = 0; e < 4; e++) {
                const int idx = v * 4 + e;
                const int p   = idx / 81;
                const int j   = idx - p * 81;
                const int xy  = j / 9;
                const int uv  = j - xy * 9;
                const float* a = s1 + p * 27 + xy * 3;
                const float* b = s2 + p * 27 + uv;
                rr[e] = (a[0] * b[0] + a[1] * b[9] + a[2] * b[18]) * n1;
            }
            o1[v] = r;
        }
    }

    // ---- out2: 64*9 = 576 floats = 144 float4 ----
    {
        float4* o2 = (float4*)(out + (long long)npairs * 81 + p0 * 9);
        if (tid < PPB * 9 / 4) {
            float4 r;
            float* rr = (float*)&r;
            #pragma unroll
            for (int e = 0; e < 4; e++) {
                const int idx = tid * 4 + e;
                const int p   = idx / 9;
                const int j   = idx - p * 9;
                const int x   = j / 3;
                const int u   = j - x * 3;
                const float* a = s1 + p * 27 + x * 9;
                const float* b = s2 + p * 27 + u;
                float s = 0.0f;
                #pragma unroll
                for (int kl = 0; kl < 9; kl++)
                    s += a[kl] * b[kl * 3];
                rr[e] = s * n2;
            }
            o2[tid] = r;
        }
    }

    // ---- out3: 64 floats, coalesced scalar stores ----
    {
        float* o3 = out + (long long)npairs * 90 + p0;
        if (tid < PPB) {
            const float* a = s1 + tid * 27;
            const float* b = s2 + tid * 27;
            float s = 0.0f;
            #pragma unroll
            for (int j = 0; j < 27; j++)
                s += a[j] * b[j];
            o3[tid] = s * n3;
        }
    }
}

extern "C" void kernel_launch(void* const* d_in, const int* in_sizes, int n_in,
                              void* d_out, int out_size)
{
    const float* T1 = (const float*)d_in[0];
    const float* T2 = (const float*)d_in[1];
    float* out = (float*)d_out;

    const int npairs = in_sizes[0] / 27;        // B*C = 1,048,576
    const int grid = npairs / PPB;              // exactly divisible (2^20/64)

    broadcast_tc_kernel<<<grid, THREADS>>>(T1, T2, out, npairs);
}

// round 3
// speedup vs baseline: 5.9007x; 1.4256x over previous
#include <cuda_runtime.h>

// BroadcastTC on GB300, round 3: per-pair register compute + smem-staged
// coalesced output. npairs = B*C = 1,048,576; t1,t2 = 27 fp32 per pair.
//   out1[xy,uv] = sum_k t1[xy*3+k]*t2[k*9+uv] / sqrt(3)   (81 floats)
//   out2[x,u]   = sum_kl t1[x*9+kl]*t2[kl*3+u] / 3        (9 floats)
//   out3        = dot(t1,t2) / sqrt(27)                   (1 float)
// Output layout: [out1 flat | out2 flat | out3 flat].

#define PPB 128       // pairs per block (2^20 divisible by 128)
#define THREADS 128

__global__ __launch_bounds__(THREADS)
void broadcast_tc_kernel(const float* __restrict__ T1,
                         const float* __restrict__ T2,
                         float* __restrict__ out,
                         int npairs)
{
    // Single reusable buffer: inputs (6912 floats) then out1 (10368 floats).
    __shared__ float s[PPB * 81];    // 41472 B static

    const int tid = threadIdx.x;
    const long long p0 = (long long)blockIdx.x * PPB;

    // ---- Stage inputs coalesced: 2 x 864 float4 ----
    {
        const float4* g1 = (const float4*)(T1 + p0 * 27);
        const float4* g2 = (const float4*)(T2 + p0 * 27);
        float4* sv = (float4*)s;
        #pragma unroll
        for (int i = tid; i < PPB * 27 / 4; i += THREADS) {
            sv[i]                 = g1[i];
            sv[PPB * 27 / 4 + i]  = g2[i];
        }
    }
    __syncthreads();

    // ---- Gather this thread's pair into registers (odd stride -> no conflicts) ----
    float a[27], b[27];
    #pragma unroll
    for (int j = 0; j < 27; j++) {
        a[j] = s[tid * 27 + j];
        b[j] = s[PPB * 27 + tid * 27 + j];
    }
    __syncthreads();   // all inputs consumed; buffer reusable

    const float n1 = 0.5773502691896258f;   // 1/sqrt(3)
    const float n2 = 0.3333333333333333f;   // 1/3
    const float n3 = 0.1924500897298753f;   // 1/sqrt(27)

    // ---- out1 into smem (stride 81 across threads: conflict-free) ----
    #pragma unroll
    for (int xy = 0; xy < 9; xy++) {
        const float c0 = a[xy * 3 + 0];
        const float c1 = a[xy * 3 + 1];
        const float c2 = a[xy * 3 + 2];
        #pragma unroll
        for (int uv = 0; uv < 9; uv++) {
            s[tid * 81 + xy * 9 + uv] =
                (c0 * b[uv] + c1 * b[9 + uv] + c2 * b[18 + uv]) * n1;
        }
    }

    // ---- out2/out3 in registers while out1 STS drains ----
    float o2r[9];
    #pragma unroll
    for (int x = 0; x < 3; x++) {
        #pragma unroll
        for (int u = 0; u < 3; u++) {
            float r = 0.0f;
            #pragma unroll
            for (int kl = 0; kl < 9; kl++)
                r += a[x * 9 + kl] * b[kl * 3 + u];
            o2r[x * 3 + u] = r * n2;
        }
    }
    float r3 = 0.0f;
    #pragma unroll
    for (int j = 0; j < 27; j++) r3 += a[j] * b[j];

    __syncthreads();

    // ---- Copy out1 coalesced: 2592 float4 per block ----
    {
        float4* o1 = (float4*)(out + p0 * 81);
        const float4* sv = (const float4*)s;
        #pragma unroll
        for (int i = tid; i < PPB * 81 / 4; i += THREADS)
            o1[i] = sv[i];
    }
    __syncthreads();   // out1 copy done reading s

    // ---- out2 via smem stage (stride 9: conflict-free), then coalesced copy ----
    #pragma unroll
    for (int j = 0; j < 9; j++)
        s[tid * 9 + j] = o2r[j];
    __syncthreads();
    {
        float4* o2 = (float4*)(out + (long long)npairs * 81 + p0 * 9);
        const float4* sv = (const float4*)s;
        #pragma unroll
        for (int i = tid; i < PPB * 9 / 4; i += THREADS)
            o2[i] = sv[i];
    }

    // ---- out3: already coalesced scalar store ----
    out[(long long)npairs * 90 + p0 + tid] = r3 * n3;
}

extern "C" void kernel_launch(void* const* d_in, const int* in_sizes, int n_in,
                              void* d_out, int out_size)
{
    const float* T1 = (const float*)d_in[0];
    const float* T2 = (const float*)d_in[1];
    float* out = (float*)d_out;

    const int npairs = in_sizes[0] / 27;     // 1,048,576
    const int grid = npairs / PPB;           // 8192

    broadcast_tc_kernel<<<grid, THREADS>>>(T1, T2, out, npairs);
}

// round 5
// speedup vs baseline: 6.7373x; 1.1418x over previous
#include <cuda_runtime.h>

// BroadcastTC on GB300, round 5: 2-threads-per-pair role split (fixes R4's
// out2 x=1 index bug). npairs = B*C = 1,048,576; t1,t2 = 27 fp32 per pair.
//   out1[xy,uv] = sum_k t1[xy*3+k]*t2[k*9+uv] / sqrt(3)   (81 floats)
//   out2[x,u]   = sum_kl t1[x*9+kl]*t2[kl*3+u] / 3        (9 floats)
//   out3        = dot(t1,t2) / sqrt(27)                   (1 float)
// Output layout: [out1 flat | out2 flat | out3 flat].
//
// Role split: thread p (role 0) and p+128 (role 1) share pair p.
//   role 0: t1[0..11]  -> out1 rows xy=0..3, out2 x=0, x=1 partial(kl=0..2),
//           out3 partial(j=0..11)
//   role 1: t1[12..26] -> out1 rows xy=4..8, out2 x=1 partial(kl=3..8), x=2,
//           out3 partial(j=12..26), combines + stores out3

#define PPB 128
#define THREADS 256

__global__ __launch_bounds__(THREADS, 4)
void broadcast_tc_kernel(const float* __restrict__ T1,
                         const float* __restrict__ T2,
                         float* __restrict__ out,
                         int npairs)
{
    __shared__ float s[PPB * 81];      // 41472 B: inputs, then out1/out2 staging
    __shared__ float aux[PPB * 4];     // 2048 B: role-0 partials (stride 4)

    const int tid  = threadIdx.x;
    const int p    = tid & (PPB - 1);
    const int role = tid >> 7;
    const long long p0 = (long long)blockIdx.x * PPB;

    // ---- Stage inputs coalesced: 2 x 864 float4 ----
    {
        const float4* g1 = (const float4*)(T1 + p0 * 27);
        const float4* g2 = (const float4*)(T2 + p0 * 27);
        float4* sv = (float4*)s;
        #pragma unroll
        for (int i = tid; i < PPB * 27 / 4; i += THREADS) {
            sv[i]                = g1[i];
            sv[PPB * 27 / 4 + i] = g2[i];
        }
    }
    __syncthreads();

    // ---- Per-role register gather (stride 27: conflict-free) ----
    // a[j] = t1_glob[role*12 + j], j = 0..14 (role 0 uses only 0..11).
    float b[27], a[15];
    #pragma unroll
    for (int j = 0; j < 27; j++) b[j] = s[PPB * 27 + p * 27 + j];
    {
        const int abase = p * 27 + role * 12;
        #pragma unroll
        for (int j = 0; j < 15; j++) a[j] = s[abase + j];
    }
    __syncthreads();   // input reads done; s reusable

    const float n1 = 0.5773502691896258f;   // 1/sqrt(3)
    const float n2 = 0.3333333333333333f;   // 1/3
    const float n3 = 0.1924500897298753f;   // 1/sqrt(27)

    if (role == 0) {
        // out1 rows xy = 0..3 (a[xy*3+k] = t1[xy*3+k])
        #pragma unroll
        for (int xy = 0; xy < 4; xy++) {
            const float c0 = a[xy * 3 + 0] * n1;
            const float c1 = a[xy * 3 + 1] * n1;
            const float c2 = a[xy * 3 + 2] * n1;
            #pragma unroll
            for (int uv = 0; uv < 9; uv++)
                s[p * 81 + xy * 9 + uv] = c0 * b[uv] + c1 * b[9 + uv] + c2 * b[18 + uv];
        }

        // out2 x=0 full: t1[kl] = a[kl], kl=0..8
        float x0[3];
        #pragma unroll
        for (int u = 0; u < 3; u++) {
            float r = 0.0f;
            #pragma unroll
            for (int kl = 0; kl < 9; kl++) r += a[kl] * b[kl * 3 + u];
            x0[u] = r * n2;
        }
        // out2 x=1 partial, kl=0..2: t1[9+kl] = a[9+kl]
        float x1p[3];
        #pragma unroll
        for (int u = 0; u < 3; u++) {
            float r = 0.0f;
            #pragma unroll
            for (int kl = 0; kl < 3; kl++) r += a[9 + kl] * b[kl * 3 + u];
            x1p[u] = r;
        }
        // out3 partial: j = 0..11
        float d = 0.0f;
        #pragma unroll
        for (int j = 0; j < 12; j++) d += a[j] * b[j];

        aux[p * 4 + 0] = x1p[0];
        aux[p * 4 + 1] = x1p[1];
        aux[p * 4 + 2] = x1p[2];
        aux[p * 4 + 3] = d;

        __syncthreads();   // out1 staged, partials published

        // copy out1 coalesced (both roles)
        {
            float4* o1 = (float4*)(out + p0 * 81);
            const float4* sv = (const float4*)s;
            for (int i = tid; i < PPB * 81 / 4; i += THREADS) o1[i] = sv[i];
        }
        __syncthreads();   // s free

        // stage out2 x=0 -> slots 0..2 (stride 9: conflict-free)
        s[p * 9 + 0] = x0[0];
        s[p * 9 + 1] = x0[1];
        s[p * 9 + 2] = x0[2];
        __syncthreads();

        // copy out2 coalesced
        {
            float4* o2 = (float4*)(out + (long long)npairs * 81 + p0 * 9);
            const float4* sv = (const float4*)s;
            for (int i = tid; i < PPB * 9 / 4; i += THREADS) o2[i] = sv[i];
        }
    } else {
        // a[j] = t1[12+j], j = 0..14
        // out1 rows xy = 4..8: t1[xy*3+k] = a[xy*3-12+k]
        #pragma unroll
        for (int xy = 4; xy < 9; xy++) {
            const float c0 = a[xy * 3 - 12] * n1;
            const float c1 = a[xy * 3 - 11] * n1;
            const float c2 = a[xy * 3 - 10] * n1;
            #pragma unroll
            for (int uv = 0; uv < 9; uv++)
                s[p * 81 + xy * 9 + uv] = c0 * b[uv] + c1 * b[9 + uv] + c2 * b[18 + uv];
        }

        // out2 x=1 partial, kl=3..8: t1[9+kl] = t1[12..17] = a[kl-3]   (R4 bug fix)
        float x1p[3];
        #pragma unroll
        for (int u = 0; u < 3; u++) {
            float r = 0.0f;
            #pragma unroll
            for (int kl = 3; kl < 9; kl++) r += a[kl - 3] * b[kl * 3 + u];
            x1p[u] = r;
        }
        // out2 x=2 full: t1[18+kl] = a[6+kl], kl=0..8
        float x2[3];
        #pragma unroll
        for (int u = 0; u < 3; u++) {
            float r = 0.0f;
            #pragma unroll
            for (int kl = 0; kl < 9; kl++) r += a[6 + kl] * b[kl * 3 + u];
            x2[u] = r * n2;
        }
        // out3 partial: j = 12..26
        float d = 0.0f;
        #pragma unroll
        for (int j = 0; j < 15; j++) d += a[j] * b[12 + j];

        __syncthreads();   // matches role-0: out1 staged, partials visible

        // out3: combine + coalesced store
        out[(long long)npairs * 90 + p0 + p] = (d + aux[p * 4 + 3]) * n3;

        // combine out2 x=1
        float x1[3];
        #pragma unroll
        for (int u = 0; u < 3; u++) x1[u] = (x1p[u] + aux[p * 4 + u]) * n2;

        // copy out1 coalesced (both roles)
        {
            float4* o1 = (float4*)(out + p0 * 81);
            const float4* sv = (const float4*)s;
            for (int i = tid; i < PPB * 81 / 4; i += THREADS) o1[i] = sv[i];
        }
        __syncthreads();   // s free

        // stage out2 x=1, x=2 -> slots 3..8
        s[p * 9 + 3] = x1[0];
        s[p * 9 + 4] = x1[1];
        s[p * 9 + 5] = x1[2];
        s[p * 9 + 6] = x2[0];
        s[p * 9 + 7] = x2[1];
        s[p * 9 + 8] = x2[2];
        __syncthreads();

        // copy out2 coalesced
        {
            float4* o2 = (float4*)(out + (long long)npairs * 81 + p0 * 9);
            const float4* sv = (const float4*)s;
            for (int i = tid; i < PPB * 9 / 4; i += THREADS) o2[i] = sv[i];
        }
    }
}

extern "C" void kernel_launch(void* const* d_in, const int* in_sizes, int n_in,
                              void* d_out, int out_size)
{
    const float* T1 = (const float*)d_in[0];
    const float* T2 = (const float*)d_in[1];
    float* out = (float*)d_out;

    const int npairs = in_sizes[0] / 27;     // 1,048,576
    const int grid = npairs / PPB;           // 8192

    broadcast_tc_kernel<<<grid, THREADS>>>(T1, T2, out, npairs);
}